// round 4
// baseline (speedup 1.0000x reference)
#include <cuda_runtime.h>
#include <math.h>

#define NB 64
#define NS 4096
#define NC 128
#define KTOP 64

#define PHY(p) ((p) ^ (((p) >> 4) & 15))

// Twiddle table: g_tw[m] = exp(-2*pi*i*m/4096)
__device__ float2 g_tw[NS];

__device__ __forceinline__ int drev4(int p) {
    unsigned br = __brev((unsigned)p) >> 20;               // 12-bit bit reversal
    return (int)(((br & 0x555u) << 1) | ((br & 0xAAAu) >> 1));
}

__device__ __forceinline__ float2 cmul(float2 a, float2 b) {
    return make_float2(a.x * b.x - a.y * b.y, a.x * b.y + a.y * b.x);
}
__device__ __forceinline__ float2 cmulc(float2 a, float2 b) {   // a * conj(b)
    return make_float2(a.x * b.x + a.y * b.y, a.y * b.x - a.x * b.y);
}

// W16^k = exp(-2*pi*i*k/16); constant-index after unroll -> immediates
__device__ __forceinline__ float2 w16c(int idx) {
    const float cr[16] = { 1.f,  0.9238795325112867f,  0.7071067811865476f,  0.3826834323650898f,
                           0.f, -0.3826834323650898f, -0.7071067811865476f, -0.9238795325112867f,
                          -1.f, -0.9238795325112867f, -0.7071067811865476f, -0.3826834323650898f,
                           0.f,  0.3826834323650898f,  0.7071067811865476f,  0.9238795325112867f };
    const float ci[16] = { 0.f, -0.3826834323650898f, -0.7071067811865476f, -0.9238795325112867f,
                          -1.f, -0.9238795325112867f, -0.7071067811865476f, -0.3826834323650898f,
                           0.f,  0.3826834323650898f,  0.7071067811865476f,  0.9238795325112867f,
                           1.f,  0.9238795325112867f,  0.7071067811865476f,  0.3826834323650898f };
    return make_float2(cr[idx], ci[idx]);
}

// forward DFT4 (omega = -i)
__device__ __forceinline__ void bf4f(float2& a, float2& b, float2& c, float2& d) {
    float2 acp = make_float2(a.x + c.x, a.y + c.y);
    float2 acm = make_float2(a.x - c.x, a.y - c.y);
    float2 bdp = make_float2(b.x + d.x, b.y + d.y);
    float2 bdm = make_float2(b.x - d.x, b.y - d.y);
    a = make_float2(acp.x + bdp.x, acp.y + bdp.y);
    b = make_float2(acm.x + bdm.y, acm.y - bdm.x);   // acm - i*bdm
    c = make_float2(acp.x - bdp.x, acp.y - bdp.y);
    d = make_float2(acm.x - bdm.y, acm.y + bdm.x);   // acm + i*bdm
}
// inverse DFT4 (omega = +i)
__device__ __forceinline__ void bf4i(float2& a, float2& b, float2& c, float2& d) {
    float2 acp = make_float2(a.x + c.x, a.y + c.y);
    float2 acm = make_float2(a.x - c.x, a.y - c.y);
    float2 bdp = make_float2(b.x + d.x, b.y + d.y);
    float2 bdm = make_float2(b.x - d.x, b.y - d.y);
    a = make_float2(acp.x + bdp.x, acp.y + bdp.y);
    b = make_float2(acm.x - bdm.y, acm.y + bdm.x);   // acm + i*bdm
    c = make_float2(acp.x - bdp.x, acp.y - bdp.y);
    d = make_float2(acm.x + bdm.y, acm.y - bdm.x);
}

// 16-pt DIF in registers: input natural, output v[i] = Y_{rev2(i)}
__device__ __forceinline__ void sixteen_fwd(float2* v) {
    #pragma unroll
    for (int c = 0; c < 4; c++) {
        bf4f(v[c], v[c + 4], v[c + 8], v[c + 12]);
        if (c) {
            #pragma unroll
            for (int m = 1; m < 4; m++)
                v[c + 4 * m] = cmul(v[c + 4 * m], w16c(c * m));
        }
    }
    #pragma unroll
    for (int b = 0; b < 4; b++)
        bf4f(v[4 * b + 0], v[4 * b + 1], v[4 * b + 2], v[4 * b + 3]);
}

// 16-pt DIT inverse: input v[i] = Z_{rev2(i)} (ext twiddles pre-applied), output natural
__device__ __forceinline__ void sixteen_inv(float2* v) {
    #pragma unroll
    for (int b = 0; b < 4; b++)
        bf4i(v[4 * b + 0], v[4 * b + 1], v[4 * b + 2], v[4 * b + 3]);
    #pragma unroll
    for (int c = 1; c < 4; c++) {
        #pragma unroll
        for (int m = 1; m < 4; m++)
            v[c + 4 * m] = cmulc(v[c + 4 * m], w16c(c * m));
    }
    #pragma unroll
    for (int c = 0; c < 4; c++)
        bf4i(v[c], v[c + 4], v[c + 8], v[c + 12]);
}

template<int S, int G>
__device__ __forceinline__ void fwd_stage(float2* Xs, int tid) {
    int blk, t;
    if (S == 16)  { blk = tid >> 4;  t = tid & 15; }
    else          { blk = tid;       t = 0;        }
    int base = blk * 16 * S + t;
    float2 v[16];
    #pragma unroll
    for (int i = 0; i < 16; i++) v[i] = Xs[PHY(base + i * S)];
    sixteen_fwd(v);
    #pragma unroll
    for (int i = 0; i < 16; i++) {
        int r = ((i & 3) << 2) | (i >> 2);
        float2 o = v[i];
        if (S != 1 && r != 0) o = cmul(o, g_tw[t * G * r]);
        Xs[PHY(base + i * S)] = o;
    }
}

template<int S, int G>
__device__ __forceinline__ void inv_stage(float2* Xs, int tid) {
    int blk, t;
    if (S == 16)  { blk = tid >> 4;  t = tid & 15; }
    else          { blk = tid;       t = 0;        }
    int base = blk * 16 * S + t;
    float2 v[16];
    #pragma unroll
    for (int i = 0; i < 16; i++) {
        int r = ((i & 3) << 2) | (i >> 2);
        float2 x = Xs[PHY(base + i * S)];
        if (S != 1 && r != 0) x = cmulc(x, g_tw[t * G * r]);
        v[i] = x;
    }
    sixteen_inv(v);
    #pragma unroll
    for (int q = 0; q < 16; q++) Xs[PHY(base + q * S)] = v[q];
}

// ---------------- twiddle init ----------------
__global__ void k_tw() {
    int m = blockIdx.x * blockDim.x + threadIdx.x;
    if (m < NS) {
        double ang = -2.0 * 3.14159265358979323846 * (double)m / (double)NS;
        g_tw[m] = make_float2((float)cos(ang), (float)sin(ang));
    }
}

// ---------------- fused: gather -> FFT -> split -> top-64 -> recombine -> iFFT -> scatter ----------------
__global__ __launch_bounds__(256) void k_fft(const float2* __restrict__ in2,
                                             float2* __restrict__ out2) {
    __shared__ float2 X[NS];
    __shared__ unsigned hA[256], hB[256];
    __shared__ unsigned sPrefA, sPrefB, sNeedA, sNeedB;

    const int tid  = threadIdx.x;
    const int pair = blockIdx.x;
    const int b    = pair >> 6;          // batch
    const int c2   = pair & 63;          // channel-pair index
    const float2* src = in2 + (size_t)b * NS * (NC / 2) + c2;
    float2*       dst = out2 + (size_t)b * NS * (NC / 2) + c2;

    // ---- load (strided gmem, L2-shared across same-b CTAs) + first fwd stage in regs ----
    float2 v[16];
    #pragma unroll
    for (int i = 0; i < 16; i++)
        v[i] = src[(size_t)(tid + 256 * i) * (NC / 2)];
    if (tid == 0) { sPrefA = 0; sPrefB = 0; sNeedA = KTOP; sNeedB = KTOP; }
    sixteen_fwd(v);
    #pragma unroll
    for (int i = 0; i < 16; i++) {
        int r = ((i & 3) << 2) | (i >> 2);
        float2 o = v[i];
        if (r) o = cmul(o, g_tw[tid * r]);
        X[PHY(tid + i * 256)] = o;
    }
    __syncthreads();

    fwd_stage<16, 16>(X, tid);  __syncthreads();
    fwd_stage<1, 256>(X, tid);
    hA[tid] = 0u; hB[tid] = 0u;
    __syncthreads();

    // ---- split Z -> A (bins 0..2047 at drev4(k)) / conj(B) (at drev4(4096-k)),
    //      fused with pass-0 (top byte) histogram ----
    {
        int kb = ((tid & 31) << 6) | ((tid >> 5) << 3);
        #pragma unroll
        for (int m = 0; m < 8; m++) {
            int k = kb + m;
            if (k) {
                int p  = PHY(drev4(k));
                int pn = PHY(drev4(NS - k));
                float2 z = X[p], zn = X[pn];
                float2 A  = make_float2(0.5f * (z.x + zn.x), 0.5f * (z.y - zn.y));
                float2 Bc = make_float2(0.5f * (z.y + zn.y), 0.5f * (zn.x - z.x));
                X[p] = A; X[pn] = Bc;
                unsigned ua = __float_as_uint(A.x * A.x + A.y * A.y);
                unsigned ub = __float_as_uint(Bc.x * Bc.x + Bc.y * Bc.y);
                atomicAdd(&hA[ua >> 24], 1u);
                atomicAdd(&hB[ub >> 24], 1u);
            } else {
                // bins 0 and 2048: self-conjugate, stored packed (A,B) as (re,im)
                float2 v0 = X[PHY(0)];
                float2 v2 = X[PHY(drev4(NS / 2))];
                atomicAdd(&hA[__float_as_uint(v0.x * v0.x) >> 24], 1u);
                atomicAdd(&hB[__float_as_uint(v0.y * v0.y) >> 24], 1u);
                atomicAdd(&hA[__float_as_uint(v2.x * v2.x) >> 24], 1u);
                atomicAdd(&hB[__float_as_uint(v2.y * v2.y) >> 24], 1u);
            }
        }
    }
    __syncthreads();
    if (tid == 0) {
        unsigned need = sNeedA, acc = 0;
        for (int bkt = 255; bkt >= 0; bkt--) {
            unsigned cnt = hA[bkt];
            if (acc + cnt >= need) { sNeedA = need - acc; sPrefA = (unsigned)bkt << 24; break; }
            acc += cnt;
        }
    }
    if (tid == 32) {
        unsigned need = sNeedB, acc = 0;
        for (int bkt = 255; bkt >= 0; bkt--) {
            unsigned cnt = hB[bkt];
            if (acc + cnt >= need) { sNeedB = need - acc; sPrefB = (unsigned)bkt << 24; break; }
            acc += cnt;
        }
    }
    __syncthreads();

    // ---- remaining 3 radix-select passes ----
    unsigned himask = 0xFF000000u;
    #pragma unroll
    for (int pass = 1; pass < 4; pass++) {
        const int shift = 24 - 8 * pass;
        hA[tid] = 0u; hB[tid] = 0u;
        __syncthreads();
        const unsigned pA = sPrefA, pB = sPrefB;
        #pragma unroll
        for (int p = tid; p < NS; p += 256) {
            int km = drev4(p);
            float2 w = X[PHY(p)];
            if (km == 0 || km == NS / 2) {
                unsigned ua = __float_as_uint(w.x * w.x);
                if ((ua & himask) == pA) atomicAdd(&hA[(ua >> shift) & 255], 1u);
                unsigned ub = __float_as_uint(w.y * w.y);
                if ((ub & himask) == pB) atomicAdd(&hB[(ub >> shift) & 255], 1u);
            } else {
                unsigned u = __float_as_uint(w.x * w.x + w.y * w.y);
                if (km < NS / 2) { if ((u & himask) == pA) atomicAdd(&hA[(u >> shift) & 255], 1u); }
                else             { if ((u & himask) == pB) atomicAdd(&hB[(u >> shift) & 255], 1u); }
            }
        }
        __syncthreads();
        if (tid == 0) {
            unsigned need = sNeedA, acc = 0;
            for (int bkt = 255; bkt >= 0; bkt--) {
                unsigned cnt = hA[bkt];
                if (acc + cnt >= need) { sNeedA = need - acc; sPrefA = pA | ((unsigned)bkt << shift); break; }
                acc += cnt;
            }
        }
        if (tid == 32) {
            unsigned need = sNeedB, acc = 0;
            for (int bkt = 255; bkt >= 0; bkt--) {
                unsigned cnt = hB[bkt];
                if (acc + cnt >= need) { sNeedB = need - acc; sPrefB = pB | ((unsigned)bkt << shift); break; }
                acc += cnt;
            }
        }
        himask = 0xFFFFFFFFu << shift;
        __syncthreads();
    }
    const float pivA = __uint_as_float(sPrefA);
    const float pivB = __uint_as_float(sPrefB);

    // ---- mask + recombine Zf = Am + i*Bm (Hermitian pair written together) ----
    {
        int kb = ((tid & 31) << 6) | ((tid >> 5) << 3);
        #pragma unroll
        for (int m = 0; m < 8; m++) {
            int k = kb + m;
            if (k) {
                int p  = PHY(drev4(k));
                int pn = PHY(drev4(NS - k));
                float2 A = X[p], Bc = X[pn];
                float ma = A.x * A.x + A.y * A.y;
                float mb = Bc.x * Bc.x + Bc.y * Bc.y;
                if (ma < pivA) A  = make_float2(0.f, 0.f);
                if (mb < pivB) Bc = make_float2(0.f, 0.f);
                X[p]  = make_float2(A.x - Bc.y, A.y + Bc.x);
                X[pn] = make_float2(A.x + Bc.y, Bc.x - A.y);
            } else {
                float2 v0 = X[PHY(0)];
                v0.x = (v0.x * v0.x >= pivA) ? v0.x : 0.f;
                v0.y = (v0.y * v0.y >= pivB) ? v0.y : 0.f;
                X[PHY(0)] = v0;
                int p2 = PHY(drev4(NS / 2));
                float2 v2 = X[p2];
                v2.x = (v2.x * v2.x >= pivA) ? v2.x : 0.f;
                v2.y = (v2.y * v2.y >= pivB) ? v2.y : 0.f;
                X[p2] = v2;
            }
        }
    }
    __syncthreads();

    inv_stage<1, 256>(X, tid);  __syncthreads();
    inv_stage<16, 16>(X, tid);  __syncthreads();

    // ---- last inverse stage in regs + direct scatter store ----
    {
        float2 u[16];
        #pragma unroll
        for (int i = 0; i < 16; i++) {
            int r = ((i & 3) << 2) | (i >> 2);
            float2 x = X[PHY(tid + i * 256)];
            if (r) x = cmulc(x, g_tw[tid * r]);
            u[i] = x;
        }
        sixteen_inv(u);
        const float invn = 1.0f / (float)NS;
        #pragma unroll
        for (int q = 0; q < 16; q++) {
            dst[(size_t)(tid + q * 256) * (NC / 2)] =
                make_float2(u[q].x * invn, u[q].y * invn);
        }
    }
}

extern "C" void kernel_launch(void* const* d_in, const int* in_sizes, int n_in,
                              void* d_out, int out_size) {
    const float2* in2 = (const float2*)d_in[0];
    float2* out2 = (float2*)d_out;

    k_tw<<<(NS + 255) / 256, 256>>>();
    k_fft<<<NB * NC / 2, 256>>>(in2, out2);
}

// round 5
// speedup vs baseline: 2.6109x; 2.6109x over previous
#include <cuda_runtime.h>
#include <math.h>

#define NB 64
#define NS 4096
#define NC 128
#define KTOP 64

#define PHY(p) ((p) ^ (((p) >> 4) & 15))

// 128 MB scratch holding the (B, C, S) transposed data; FFT operates in-place on rows.
__device__ float g_tr[(size_t)NB * NC * NS];
// Twiddle table: g_tw[m] = exp(-2*pi*i*m/4096)
__device__ float2 g_tw[NS];

__device__ __forceinline__ int drev4(int p) {
    unsigned br = __brev((unsigned)p) >> 20;               // 12-bit bit reversal
    return (int)(((br & 0x555u) << 1) | ((br & 0xAAAu) >> 1));
}

__device__ __forceinline__ float2 cmul(float2 a, float2 b) {
    return make_float2(a.x * b.x - a.y * b.y, a.x * b.y + a.y * b.x);
}
__device__ __forceinline__ float2 cmulc(float2 a, float2 b) {   // a * conj(b)
    return make_float2(a.x * b.x + a.y * b.y, a.y * b.x - a.x * b.y);
}

// W16^k = exp(-2*pi*i*k/16); constant-index after unroll -> immediates
__device__ __forceinline__ float2 w16c(int idx) {
    const float cr[16] = { 1.f,  0.9238795325112867f,  0.7071067811865476f,  0.3826834323650898f,
                           0.f, -0.3826834323650898f, -0.7071067811865476f, -0.9238795325112867f,
                          -1.f, -0.9238795325112867f, -0.7071067811865476f, -0.3826834323650898f,
                           0.f,  0.3826834323650898f,  0.7071067811865476f,  0.9238795325112867f };
    const float ci[16] = { 0.f, -0.3826834323650898f, -0.7071067811865476f, -0.9238795325112867f,
                          -1.f, -0.9238795325112867f, -0.7071067811865476f, -0.3826834323650898f,
                           0.f,  0.3826834323650898f,  0.7071067811865476f,  0.9238795325112867f,
                           1.f,  0.9238795325112867f,  0.7071067811865476f,  0.3826834323650898f };
    return make_float2(cr[idx], ci[idx]);
}

// forward DFT4 (omega = -i)
__device__ __forceinline__ void bf4f(float2& a, float2& b, float2& c, float2& d) {
    float2 acp = make_float2(a.x + c.x, a.y + c.y);
    float2 acm = make_float2(a.x - c.x, a.y - c.y);
    float2 bdp = make_float2(b.x + d.x, b.y + d.y);
    float2 bdm = make_float2(b.x - d.x, b.y - d.y);
    a = make_float2(acp.x + bdp.x, acp.y + bdp.y);
    b = make_float2(acm.x + bdm.y, acm.y - bdm.x);   // acm - i*bdm
    c = make_float2(acp.x - bdp.x, acp.y - bdp.y);
    d = make_float2(acm.x - bdm.y, acm.y + bdm.x);   // acm + i*bdm
}
// inverse DFT4 (omega = +i)
__device__ __forceinline__ void bf4i(float2& a, float2& b, float2& c, float2& d) {
    float2 acp = make_float2(a.x + c.x, a.y + c.y);
    float2 acm = make_float2(a.x - c.x, a.y - c.y);
    float2 bdp = make_float2(b.x + d.x, b.y + d.y);
    float2 bdm = make_float2(b.x - d.x, b.y - d.y);
    a = make_float2(acp.x + bdp.x, acp.y + bdp.y);
    b = make_float2(acm.x - bdm.y, acm.y + bdm.x);   // acm + i*bdm
    c = make_float2(acp.x - bdp.x, acp.y - bdp.y);
    d = make_float2(acm.x + bdm.y, acm.y - bdm.x);
}

// 16-pt DIF in registers: input natural, output v[i] = Y_{rev2(i)}
__device__ __forceinline__ void sixteen_fwd(float2* v) {
    #pragma unroll
    for (int c = 0; c < 4; c++) {
        bf4f(v[c], v[c + 4], v[c + 8], v[c + 12]);
        if (c) {
            #pragma unroll
            for (int m = 1; m < 4; m++)
                v[c + 4 * m] = cmul(v[c + 4 * m], w16c(c * m));
        }
    }
    #pragma unroll
    for (int b = 0; b < 4; b++)
        bf4f(v[4 * b + 0], v[4 * b + 1], v[4 * b + 2], v[4 * b + 3]);
}

// 16-pt DIT inverse: input v[i] = Z_{rev2(i)} (ext twiddles pre-applied), output natural
__device__ __forceinline__ void sixteen_inv(float2* v) {
    #pragma unroll
    for (int b = 0; b < 4; b++)
        bf4i(v[4 * b + 0], v[4 * b + 1], v[4 * b + 2], v[4 * b + 3]);
    #pragma unroll
    for (int c = 1; c < 4; c++) {
        #pragma unroll
        for (int m = 1; m < 4; m++)
            v[c + 4 * m] = cmulc(v[c + 4 * m], w16c(c * m));
    }
    #pragma unroll
    for (int c = 0; c < 4; c++)
        bf4i(v[c], v[c + 4], v[c + 8], v[c + 12]);
}

template<int S, int G>
__device__ __forceinline__ void fwd_stage(float2* Xs, int tid) {
    int blk, t;
    if (S == 16)  { blk = tid >> 4;  t = tid & 15; }
    else          { blk = tid;       t = 0;        }
    int base = blk * 16 * S + t;
    float2 v[16];
    #pragma unroll
    for (int i = 0; i < 16; i++) v[i] = Xs[PHY(base + i * S)];
    sixteen_fwd(v);
    #pragma unroll
    for (int i = 0; i < 16; i++) {
        int r = ((i & 3) << 2) | (i >> 2);
        float2 o = v[i];
        if (S != 1 && r != 0) o = cmul(o, g_tw[t * G * r]);
        Xs[PHY(base + i * S)] = o;
    }
}

template<int S, int G>
__device__ __forceinline__ void inv_stage(float2* Xs, int tid) {
    int blk, t;
    if (S == 16)  { blk = tid >> 4;  t = tid & 15; }
    else          { blk = tid;       t = 0;        }
    int base = blk * 16 * S + t;
    float2 v[16];
    #pragma unroll
    for (int i = 0; i < 16; i++) {
        int r = ((i & 3) << 2) | (i >> 2);
        float2 x = Xs[PHY(base + i * S)];
        if (S != 1 && r != 0) x = cmulc(x, g_tw[t * G * r]);
        v[i] = x;
    }
    sixteen_inv(v);
    #pragma unroll
    for (int q = 0; q < 16; q++) Xs[PHY(base + q * S)] = v[q];
}

// Warp-parallel descending radix-select step over a 256-bucket histogram.
// Exactly one lane finds the pivot bucket and updates (sPref, sNeed).
__device__ __forceinline__ void warp_select(const unsigned* hist, unsigned* sPref,
                                            unsigned* sNeed, int shift, unsigned prefOld) {
    const int lane = threadIdx.x & 31;
    unsigned c[8];
    unsigned s = 0;
    #pragma unroll
    for (int j = 0; j < 8; j++) { c[j] = hist[lane * 8 + j]; s += c[j]; }
    unsigned incl = s;
    #pragma unroll
    for (int d = 1; d < 32; d <<= 1) {
        unsigned t = __shfl_up_sync(0xFFFFFFFFu, incl, d);
        if (lane >= d) incl += t;
    }
    unsigned total = __shfl_sync(0xFFFFFFFFu, incl, 31);
    unsigned above = total - incl;              // sum of all higher lanes' groups
    const unsigned need = *sNeed;
    unsigned acc = above;
    #pragma unroll
    for (int j = 7; j >= 0; j--) {
        unsigned cj = c[j];
        if (acc < need && acc + cj >= need) {
            *sNeed = need - acc;
            *sPref = prefOld | ((unsigned)(lane * 8 + j) << shift);
        }
        acc += cj;
    }
}

// ---------------- twiddle init ----------------
__global__ void k_tw() {
    int m = blockIdx.x * blockDim.x + threadIdx.x;
    if (m < NS) {
        double ang = -2.0 * 3.14159265358979323846 * (double)m / (double)NS;
        g_tw[m] = make_float2((float)cos(ang), (float)sin(ang));
    }
}

// ---------------- transpose (B,S,C) -> scratch (B,C,S) ----------------
__global__ void k_t1(const float* __restrict__ in) {
    __shared__ float tile[32][33];
    int b  = blockIdx.z;
    int c0 = blockIdx.x * 32;
    int s0 = blockIdx.y * 32;
    #pragma unroll
    for (int i = threadIdx.y; i < 32; i += 8)
        tile[i][threadIdx.x] = in[((size_t)b * NS + (s0 + i)) * NC + (c0 + threadIdx.x)];
    __syncthreads();
    #pragma unroll
    for (int i = threadIdx.y; i < 32; i += 8)
        g_tr[((size_t)b * NC + (c0 + i)) * NS + (s0 + threadIdx.x)] = tile[threadIdx.x][i];
}

// ---------------- transpose scratch (B,C,S) -> out (B,S,C) ----------------
__global__ void k_t3(float* __restrict__ out) {
    __shared__ float tile[32][33];
    int b  = blockIdx.z;
    int c0 = blockIdx.x * 32;
    int s0 = blockIdx.y * 32;
    #pragma unroll
    for (int i = threadIdx.y; i < 32; i += 8)
        tile[i][threadIdx.x] = g_tr[((size_t)b * NC + (c0 + i)) * NS + (s0 + threadIdx.x)];
    __syncthreads();
    #pragma unroll
    for (int i = threadIdx.y; i < 32; i += 8)
        out[((size_t)b * NS + (s0 + i)) * NC + (c0 + threadIdx.x)] = tile[threadIdx.x][i];
}

// ---------------- paired-channel: load+FFT -> split -> top-64 -> recombine -> iFFT+store ----------------
__global__ __launch_bounds__(256, 3) void k_fft() {
    __shared__ float2 X[NS];
    __shared__ unsigned hA[2][256], hB[2][256];
    __shared__ unsigned sPrefA, sPrefB, sNeedA, sNeedB;

    const int tid = threadIdx.x;
    const size_t row = (size_t)blockIdx.x * 2 * NS;
    const float* ap = g_tr + row;
    const float* bp = g_tr + row + NS;

    // ---- coalesced load + first fwd stage (S=256) in regs ----
    {
        float2 v[16];
        #pragma unroll
        for (int i = 0; i < 16; i++)
            v[i] = make_float2(ap[tid + 256 * i], bp[tid + 256 * i]);
        if (tid == 0) { sPrefA = 0; sPrefB = 0; sNeedA = KTOP; sNeedB = KTOP; }
        hA[0][tid] = 0u; hB[0][tid] = 0u;
        sixteen_fwd(v);
        #pragma unroll
        for (int i = 0; i < 16; i++) {
            int r = ((i & 3) << 2) | (i >> 2);
            float2 o = v[i];
            if (r) o = cmul(o, g_tw[tid * r]);
            X[PHY(tid + i * 256)] = o;
        }
    }
    __syncthreads();

    fwd_stage<16, 16>(X, tid);  __syncthreads();
    fwd_stage<1, 256>(X, tid);  __syncthreads();

    // ---- split Z -> A / conj(B), fused with pass-0 histogram (buf 0); zero buf 1 ----
    hA[1][tid] = 0u; hB[1][tid] = 0u;
    {
        int kb = ((tid & 31) << 6) | ((tid >> 5) << 3);
        #pragma unroll
        for (int m = 0; m < 8; m++) {
            int k = kb + m;
            if (k) {
                int p  = PHY(drev4(k));
                int pn = PHY(drev4(NS - k));
                float2 z = X[p], zn = X[pn];
                float2 A  = make_float2(0.5f * (z.x + zn.x), 0.5f * (z.y - zn.y));
                float2 Bc = make_float2(0.5f * (z.y + zn.y), 0.5f * (zn.x - z.x));
                X[p] = A; X[pn] = Bc;
                unsigned ua = __float_as_uint(A.x * A.x + A.y * A.y);
                unsigned ub = __float_as_uint(Bc.x * Bc.x + Bc.y * Bc.y);
                atomicAdd(&hA[0][ua >> 24], 1u);
                atomicAdd(&hB[0][ub >> 24], 1u);
            } else {
                float2 v0 = X[PHY(0)];
                float2 v2 = X[PHY(drev4(NS / 2))];
                atomicAdd(&hA[0][__float_as_uint(v0.x * v0.x) >> 24], 1u);
                atomicAdd(&hB[0][__float_as_uint(v0.y * v0.y) >> 24], 1u);
                atomicAdd(&hA[0][__float_as_uint(v2.x * v2.x) >> 24], 1u);
                atomicAdd(&hB[0][__float_as_uint(v2.y * v2.y) >> 24], 1u);
            }
        }
    }
    __syncthreads();
    if (tid < 32)            warp_select(hA[0], &sPrefA, &sNeedA, 24, 0u);
    else if (tid < 64)       warp_select(hB[0], &sPrefB, &sNeedB, 24, 0u);
    __syncthreads();

    // ---- remaining 3 radix-select passes (double-buffered histograms) ----
    unsigned himask = 0xFF000000u;
    #pragma unroll
    for (int pass = 1; pass < 4; pass++) {
        const int shift = 24 - 8 * pass;
        const int buf   = pass & 1;
        const unsigned pA = sPrefA, pB = sPrefB;
        // zero the other buffer while accumulating into this one
        hA[buf ^ 1][tid] = 0u; hB[buf ^ 1][tid] = 0u;
        #pragma unroll
        for (int p = tid; p < NS; p += 256) {
            int km = drev4(p);
            float2 w = X[PHY(p)];
            if (km == 0 || km == NS / 2) {
                unsigned ua = __float_as_uint(w.x * w.x);
                if ((ua & himask) == pA) atomicAdd(&hA[buf][(ua >> shift) & 255], 1u);
                unsigned ub = __float_as_uint(w.y * w.y);
                if ((ub & himask) == pB) atomicAdd(&hB[buf][(ub >> shift) & 255], 1u);
            } else {
                unsigned u = __float_as_uint(w.x * w.x + w.y * w.y);
                if (km < NS / 2) { if ((u & himask) == pA) atomicAdd(&hA[buf][(u >> shift) & 255], 1u); }
                else             { if ((u & himask) == pB) atomicAdd(&hB[buf][(u >> shift) & 255], 1u); }
            }
        }
        __syncthreads();
        if (tid < 32)        warp_select(hA[buf], &sPrefA, &sNeedA, shift, pA);
        else if (tid < 64)   warp_select(hB[buf], &sPrefB, &sNeedB, shift, pB);
        himask = 0xFFFFFFFFu << shift;
        __syncthreads();
    }
    const float pivA = __uint_as_float(sPrefA);
    const float pivB = __uint_as_float(sPrefB);

    // ---- mask + recombine Zf = Am + i*Bm (Hermitian pair written together) ----
    {
        int kb = ((tid & 31) << 6) | ((tid >> 5) << 3);
        #pragma unroll
        for (int m = 0; m < 8; m++) {
            int k = kb + m;
            if (k) {
                int p  = PHY(drev4(k));
                int pn = PHY(drev4(NS - k));
                float2 A = X[p], Bc = X[pn];
                float ma = A.x * A.x + A.y * A.y;
                float mb = Bc.x * Bc.x + Bc.y * Bc.y;
                if (ma < pivA) A  = make_float2(0.f, 0.f);
                if (mb < pivB) Bc = make_float2(0.f, 0.f);
                X[p]  = make_float2(A.x - Bc.y, A.y + Bc.x);
                X[pn] = make_float2(A.x + Bc.y, Bc.x - A.y);
            } else {
                float2 v0 = X[PHY(0)];
                v0.x = (v0.x * v0.x >= pivA) ? v0.x : 0.f;
                v0.y = (v0.y * v0.y >= pivB) ? v0.y : 0.f;
                X[PHY(0)] = v0;
                int p2 = PHY(drev4(NS / 2));
                float2 v2 = X[p2];
                v2.x = (v2.x * v2.x >= pivA) ? v2.x : 0.f;
                v2.y = (v2.y * v2.y >= pivB) ? v2.y : 0.f;
                X[p2] = v2;
            }
        }
    }
    __syncthreads();

    inv_stage<1, 256>(X, tid);  __syncthreads();
    inv_stage<16, 16>(X, tid);  __syncthreads();

    // ---- last inverse stage (S=256) in regs + coalesced store ----
    {
        float2 u[16];
        #pragma unroll
        for (int i = 0; i < 16; i++) {
            int r = ((i & 3) << 2) | (i >> 2);
            float2 x = X[PHY(tid + i * 256)];
            if (r) x = cmulc(x, g_tw[tid * r]);
            u[i] = x;
        }
        sixteen_inv(u);
        const float invn = 1.0f / (float)NS;
        float* ao = g_tr + row;
        float* bo = g_tr + row + NS;
        #pragma unroll
        for (int q = 0; q < 16; q++) {
            ao[tid + q * 256] = u[q].x * invn;
            bo[tid + q * 256] = u[q].y * invn;
        }
    }
}

extern "C" void kernel_launch(void* const* d_in, const int* in_sizes, int n_in,
                              void* d_out, int out_size) {
    const float* in = (const float*)d_in[0];
    float* out = (float*)d_out;

    k_tw<<<(NS + 255) / 256, 256>>>();

    dim3 bt(32, 8);
    dim3 gt(NC / 32, NS / 32, NB);
    k_t1<<<gt, bt>>>(in);

    k_fft<<<NB * NC / 2, 256>>>();

    k_t3<<<gt, bt>>>(out);
}

// round 8
// speedup vs baseline: 3.3032x; 1.2652x over previous
#include <cuda_runtime.h>
#include <math.h>

#define NB 64
#define NS 4096
#define NC 128
#define KTOP 64

#define PHY(p) ((p) ^ (((p) >> 4) & 15))

// 128 MB scratch holding the (B, C, S) transposed data; FFT operates in-place on rows.
__device__ float g_tr[(size_t)NB * NC * NS];
// Twiddle table: g_tw[m] = exp(-2*pi*i*m/4096)
__device__ float2 g_tw[NS];

__device__ __forceinline__ int drev4(int p) {
    unsigned br = __brev((unsigned)p) >> 20;               // 12-bit bit reversal
    return (int)(((br & 0x555u) << 1) | ((br & 0xAAAu) >> 1));
}

__device__ __forceinline__ float2 cmul(float2 a, float2 b) {
    return make_float2(a.x * b.x - a.y * b.y, a.x * b.y + a.y * b.x);
}
__device__ __forceinline__ float2 cmulc(float2 a, float2 b) {   // a * conj(b)
    return make_float2(a.x * b.x + a.y * b.y, a.y * b.x - a.x * b.y);
}

// W16^k = exp(-2*pi*i*k/16); constant-index after unroll -> immediates
__device__ __forceinline__ float2 w16c(int idx) {
    const float cr[16] = { 1.f,  0.9238795325112867f,  0.7071067811865476f,  0.3826834323650898f,
                           0.f, -0.3826834323650898f, -0.7071067811865476f, -0.9238795325112867f,
                          -1.f, -0.9238795325112867f, -0.7071067811865476f, -0.3826834323650898f,
                           0.f,  0.3826834323650898f,  0.7071067811865476f,  0.9238795325112867f };
    const float ci[16] = { 0.f, -0.3826834323650898f, -0.7071067811865476f, -0.9238795325112867f,
                          -1.f, -0.9238795325112867f, -0.7071067811865476f, -0.3826834323650898f,
                           0.f,  0.3826834323650898f,  0.7071067811865476f,  0.9238795325112867f,
                           1.f,  0.9238795325112867f,  0.7071067811865476f,  0.3826834323650898f };
    return make_float2(cr[idx], ci[idx]);
}

// forward DFT4 (omega = -i)
__device__ __forceinline__ void bf4f(float2& a, float2& b, float2& c, float2& d) {
    float2 acp = make_float2(a.x + c.x, a.y + c.y);
    float2 acm = make_float2(a.x - c.x, a.y - c.y);
    float2 bdp = make_float2(b.x + d.x, b.y + d.y);
    float2 bdm = make_float2(b.x - d.x, b.y - d.y);
    a = make_float2(acp.x + bdp.x, acp.y + bdp.y);
    b = make_float2(acm.x + bdm.y, acm.y - bdm.x);   // acm - i*bdm
    c = make_float2(acp.x - bdp.x, acp.y - bdp.y);
    d = make_float2(acm.x - bdm.y, acm.y + bdm.x);   // acm + i*bdm
}
// inverse DFT4 (omega = +i)
__device__ __forceinline__ void bf4i(float2& a, float2& b, float2& c, float2& d) {
    float2 acp = make_float2(a.x + c.x, a.y + c.y);
    float2 acm = make_float2(a.x - c.x, a.y - c.y);
    float2 bdp = make_float2(b.x + d.x, b.y + d.y);
    float2 bdm = make_float2(b.x - d.x, b.y - d.y);
    a = make_float2(acp.x + bdp.x, acp.y + bdp.y);
    b = make_float2(acm.x - bdm.y, acm.y + bdm.x);   // acm + i*bdm
    c = make_float2(acp.x - bdp.x, acp.y - bdp.y);
    d = make_float2(acm.x + bdm.y, acm.y - bdm.x);
}

// 16-pt DIF in registers: input natural, output v[i] = Y_{rev2(i)}
__device__ __forceinline__ void sixteen_fwd(float2* v) {
    #pragma unroll
    for (int c = 0; c < 4; c++) {
        bf4f(v[c], v[c + 4], v[c + 8], v[c + 12]);
        if (c) {
            #pragma unroll
            for (int m = 1; m < 4; m++)
                v[c + 4 * m] = cmul(v[c + 4 * m], w16c(c * m));
        }
    }
    #pragma unroll
    for (int b = 0; b < 4; b++)
        bf4f(v[4 * b + 0], v[4 * b + 1], v[4 * b + 2], v[4 * b + 3]);
}

// 16-pt DIT inverse: input v[i] = Z_{rev2(i)} (ext twiddles pre-applied), output natural
__device__ __forceinline__ void sixteen_inv(float2* v) {
    #pragma unroll
    for (int b = 0; b < 4; b++)
        bf4i(v[4 * b + 0], v[4 * b + 1], v[4 * b + 2], v[4 * b + 3]);
    #pragma unroll
    for (int c = 1; c < 4; c++) {
        #pragma unroll
        for (int m = 1; m < 4; m++)
            v[c + 4 * m] = cmulc(v[c + 4 * m], w16c(c * m));
    }
    #pragma unroll
    for (int c = 0; c < 4; c++)
        bf4i(v[c], v[c + 4], v[c + 8], v[c + 12]);
}

template<int S, int G>
__device__ __forceinline__ void fwd_stage(float2* Xs, int tid) {
    int blk, t;
    if (S == 16)  { blk = tid >> 4;  t = tid & 15; }
    else          { blk = tid;       t = 0;        }
    int base = blk * 16 * S + t;
    float2 v[16];
    #pragma unroll
    for (int i = 0; i < 16; i++) v[i] = Xs[PHY(base + i * S)];
    sixteen_fwd(v);
    #pragma unroll
    for (int i = 0; i < 16; i++) {
        int r = ((i & 3) << 2) | (i >> 2);
        float2 o = v[i];
        if (S != 1 && r != 0) o = cmul(o, g_tw[t * G * r]);
        Xs[PHY(base + i * S)] = o;
    }
}

template<int S, int G>
__device__ __forceinline__ void inv_stage(float2* Xs, int tid) {
    int blk, t;
    if (S == 16)  { blk = tid >> 4;  t = tid & 15; }
    else          { blk = tid;       t = 0;        }
    int base = blk * 16 * S + t;
    float2 v[16];
    #pragma unroll
    for (int i = 0; i < 16; i++) {
        int r = ((i & 3) << 2) | (i >> 2);
        float2 x = Xs[PHY(base + i * S)];
        if (S != 1 && r != 0) x = cmulc(x, g_tw[t * G * r]);
        v[i] = x;
    }
    sixteen_inv(v);
    #pragma unroll
    for (int q = 0; q < 16; q++) Xs[PHY(base + q * S)] = v[q];
}

// Warp-parallel descending radix-select step over a 256-bucket histogram.
__device__ __forceinline__ void warp_select(const unsigned* hist, unsigned* sPref,
                                            unsigned* sNeed, int shift, unsigned prefOld) {
    const int lane = threadIdx.x & 31;
    unsigned c[8];
    unsigned s = 0;
    #pragma unroll
    for (int j = 0; j < 8; j++) { c[j] = hist[lane * 8 + j]; s += c[j]; }
    unsigned incl = s;
    #pragma unroll
    for (int d = 1; d < 32; d <<= 1) {
        unsigned t = __shfl_up_sync(0xFFFFFFFFu, incl, d);
        if (lane >= d) incl += t;
    }
    unsigned total = __shfl_sync(0xFFFFFFFFu, incl, 31);
    unsigned above = total - incl;
    const unsigned need = *sNeed;
    unsigned acc = above;
    #pragma unroll
    for (int j = 7; j >= 0; j--) {
        unsigned cj = c[j];
        if (acc < need && acc + cj >= need) {
            *sNeed = need - acc;
            *sPref = prefOld | ((unsigned)(lane * 8 + j) << shift);
        }
        acc += cj;
    }
}

// ---------------- twiddle init ----------------
__global__ void k_tw() {
    int m = blockIdx.x * blockDim.x + threadIdx.x;
    if (m < NS) {
        double ang = -2.0 * 3.14159265358979323846 * (double)m / (double)NS;
        g_tw[m] = make_float2((float)cos(ang), (float)sin(ang));
    }
}

// ---------------- transpose (B,S,C) -> scratch (B,C,S), float4 both sides ----------------
__global__ __launch_bounds__(256) void k_t1(const float* __restrict__ in) {
    __shared__ float tile[32][33];
    const int b  = blockIdx.z;
    const int c0 = blockIdx.x * 32;
    const int s0 = blockIdx.y * 32;
    const int tid = threadIdx.x;
    const int q = tid & 7;       // quad index
    const int r = tid >> 3;      // row 0..31

    // load: float4 along C
    float4 lv = *(const float4*)&in[((size_t)b * NS + (s0 + r)) * NC + c0 + 4 * q];
    tile[r][4 * q + 0] = lv.x;
    tile[r][4 * q + 1] = lv.y;
    tile[r][4 * q + 2] = lv.z;
    tile[r][4 * q + 3] = lv.w;
    __syncthreads();

    // store: float4 along S
    float4 sv;
    sv.x = tile[4 * q + 0][r];
    sv.y = tile[4 * q + 1][r];
    sv.z = tile[4 * q + 2][r];
    sv.w = tile[4 * q + 3][r];
    *(float4*)&g_tr[((size_t)b * NC + (c0 + r)) * NS + s0 + 4 * q] = sv;
}

// ---------------- transpose scratch (B,C,S) -> out (B,S,C), float4 both sides ----------------
__global__ __launch_bounds__(256) void k_t3(float* __restrict__ out) {
    __shared__ float tile[32][33];
    const int b  = blockIdx.z;
    const int c0 = blockIdx.x * 32;
    const int s0 = blockIdx.y * 32;
    const int tid = threadIdx.x;
    const int q = tid & 7;
    const int r = tid >> 3;      // c-row on load, s-row on store

    // load: float4 along S (tile indexed [c][s])
    float4 lv = *(const float4*)&g_tr[((size_t)b * NC + (c0 + r)) * NS + s0 + 4 * q];
    tile[r][4 * q + 0] = lv.x;
    tile[r][4 * q + 1] = lv.y;
    tile[r][4 * q + 2] = lv.z;
    tile[r][4 * q + 3] = lv.w;
    __syncthreads();

    // store: float4 along C
    float4 sv;
    sv.x = tile[4 * q + 0][r];
    sv.y = tile[4 * q + 1][r];
    sv.z = tile[4 * q + 2][r];
    sv.w = tile[4 * q + 3][r];
    *(float4*)&out[((size_t)b * NS + (s0 + r)) * NC + c0 + 4 * q] = sv;
}

// ---------------- paired-channel: load+FFT -> split -> top-64 -> recombine -> iFFT+store ----------------
__global__ __launch_bounds__(256, 3) void k_fft() {
    __shared__ float2 X[NS];
    __shared__ unsigned hA[2][256], hB[2][256];
    __shared__ unsigned sPrefA, sPrefB, sNeedA, sNeedB;

    const int tid = threadIdx.x;
    const size_t row = (size_t)blockIdx.x * 2 * NS;
    const float* ap = g_tr + row;
    const float* bp = g_tr + row + NS;

    // ---- coalesced load + first fwd stage (S=256) in regs ----
    {
        float2 v[16];
        #pragma unroll
        for (int i = 0; i < 16; i++)
            v[i] = make_float2(ap[tid + 256 * i], bp[tid + 256 * i]);
        if (tid == 0) { sPrefA = 0; sPrefB = 0; sNeedA = KTOP; sNeedB = KTOP; }
        hA[0][tid] = 0u; hB[0][tid] = 0u;
        sixteen_fwd(v);
        #pragma unroll
        for (int i = 0; i < 16; i++) {
            int r = ((i & 3) << 2) | (i >> 2);
            float2 o = v[i];
            if (r) o = cmul(o, g_tw[tid * r]);
            X[PHY(tid + i * 256)] = o;
        }
    }
    __syncthreads();

    fwd_stage<16, 16>(X, tid);  __syncthreads();
    fwd_stage<1, 256>(X, tid);  __syncthreads();

    // ---- split Z -> A / conj(B), cache magnitudes in regs, fused pass-0 histogram ----
    unsigned uA[8], uB[8];
    unsigned uA2 = 0u, uB2 = 0u;     // bin-2048 mags (only tid 0 meaningful)
    const int kb = ((tid & 31) << 6) | ((tid >> 5) << 3);
    hA[1][tid] = 0u; hB[1][tid] = 0u;
    #pragma unroll
    for (int m = 0; m < 8; m++) {
        int k = kb + m;
        if (k) {
            int p  = PHY(drev4(k));
            int pn = PHY(drev4(NS - k));
            float2 z = X[p], zn = X[pn];
            float2 A  = make_float2(0.5f * (z.x + zn.x), 0.5f * (z.y - zn.y));
            float2 Bc = make_float2(0.5f * (z.y + zn.y), 0.5f * (zn.x - z.x));
            X[p] = A; X[pn] = Bc;
            uA[m] = __float_as_uint(A.x * A.x + A.y * A.y);
            uB[m] = __float_as_uint(Bc.x * Bc.x + Bc.y * Bc.y);
            atomicAdd(&hA[0][uA[m] >> 24], 1u);
            atomicAdd(&hB[0][uB[m] >> 24], 1u);
        } else {
            // tid==0, m==0: bins 0 and 2048 (self-conjugate, packed (A,B) as (re,im))
            float2 v0 = X[PHY(0)];
            float2 v2 = X[PHY(drev4(NS / 2))];
            uA[0] = __float_as_uint(v0.x * v0.x);
            uB[0] = __float_as_uint(v0.y * v0.y);
            uA2   = __float_as_uint(v2.x * v2.x);
            uB2   = __float_as_uint(v2.y * v2.y);
            atomicAdd(&hA[0][uA[0] >> 24], 1u);
            atomicAdd(&hB[0][uB[0] >> 24], 1u);
            atomicAdd(&hA[0][uA2 >> 24], 1u);
            atomicAdd(&hB[0][uB2 >> 24], 1u);
        }
    }
    __syncthreads();
    if (tid < 32)            warp_select(hA[0], &sPrefA, &sNeedA, 24, 0u);
    else if (tid < 64)       warp_select(hB[0], &sPrefB, &sNeedB, 24, 0u);
    __syncthreads();

    // ---- remaining 3 radix-select passes, fully register-sourced ----
    unsigned himask = 0xFF000000u;
    #pragma unroll
    for (int pass = 1; pass < 4; pass++) {
        const int shift = 24 - 8 * pass;
        const int buf   = pass & 1;
        const unsigned pA = sPrefA, pB = sPrefB;
        hA[buf ^ 1][tid] = 0u; hB[buf ^ 1][tid] = 0u;
        #pragma unroll
        for (int m = 0; m < 8; m++) {
            unsigned ua = uA[m];
            if ((ua & himask) == pA) atomicAdd(&hA[buf][(ua >> shift) & 255], 1u);
            unsigned ub = uB[m];
            if ((ub & himask) == pB) atomicAdd(&hB[buf][(ub >> shift) & 255], 1u);
        }
        if (tid == 0) {
            if ((uA2 & himask) == pA) atomicAdd(&hA[buf][(uA2 >> shift) & 255], 1u);
            if ((uB2 & himask) == pB) atomicAdd(&hB[buf][(uB2 >> shift) & 255], 1u);
        }
        __syncthreads();
        if (tid < 32)        warp_select(hA[buf], &sPrefA, &sNeedA, shift, pA);
        else if (tid < 64)   warp_select(hB[buf], &sPrefB, &sNeedB, shift, pB);
        himask = 0xFFFFFFFFu << shift;
        __syncthreads();
    }
    const unsigned pivA = sPrefA;   // uint compare == float compare (non-negative)
    const unsigned pivB = sPrefB;

    // ---- mask (register mags vs pivot) + recombine Zf = Am + i*Bm ----
    #pragma unroll
    for (int m = 0; m < 8; m++) {
        int k = kb + m;
        if (k) {
            int p  = PHY(drev4(k));
            int pn = PHY(drev4(NS - k));
            float2 A = X[p], Bc = X[pn];
            if (uA[m] < pivA) A  = make_float2(0.f, 0.f);
            if (uB[m] < pivB) Bc = make_float2(0.f, 0.f);
            X[p]  = make_float2(A.x - Bc.y, A.y + Bc.x);
            X[pn] = make_float2(A.x + Bc.y, Bc.x - A.y);
        } else {
            float2 v0 = X[PHY(0)];
            v0.x = (uA[0] >= pivA) ? v0.x : 0.f;
            v0.y = (uB[0] >= pivB) ? v0.y : 0.f;
            X[PHY(0)] = v0;
            int p2 = PHY(drev4(NS / 2));
            float2 v2 = X[p2];
            v2.x = (uA2 >= pivA) ? v2.x : 0.f;
            v2.y = (uB2 >= pivB) ? v2.y : 0.f;
            X[p2] = v2;
        }
    }
    __syncthreads();

    inv_stage<1, 256>(X, tid);  __syncthreads();
    inv_stage<16, 16>(X, tid);  __syncthreads();

    // ---- last inverse stage (S=256) in regs + coalesced store ----
    {
        float2 u[16];
        #pragma unroll
        for (int i = 0; i < 16; i++) {
            int r = ((i & 3) << 2) | (i >> 2);
            float2 x = X[PHY(tid + i * 256)];
            if (r) x = cmulc(x, g_tw[tid * r]);
            u[i] = x;
        }
        sixteen_inv(u);
        const float invn = 1.0f / (float)NS;
        float* ao = g_tr + row;
        float* bo = g_tr + row + NS;
        #pragma unroll
        for (int q = 0; q < 16; q++) {
            ao[tid + q * 256] = u[q].x * invn;
            bo[tid + q * 256] = u[q].y * invn;
        }
    }
}

extern "C" void kernel_launch(void* const* d_in, const int* in_sizes, int n_in,
                              void* d_out, int out_size) {
    const float* in = (const float*)d_in[0];
    float* out = (float*)d_out;

    k_tw<<<(NS + 255) / 256, 256>>>();

    dim3 gt(NC / 32, NS / 32, NB);
    k_t1<<<gt, 256>>>(in);

    k_fft<<<NB * NC / 2, 256>>>();

    k_t3<<<gt, 256>>>(out);
}